// round 8
// baseline (speedup 1.0000x reference)
#include <cuda_runtime.h>

#define TWO_PI_F 6.283185307179586f
#define NROT 8
#define C_DIM 128
#define KS 5
#define PATCH 25
#define TPB 256
#define CIN_CHUNK 32
#define NACT 13
#define OGRP 4
#define ACT_MASK 0x477DC4u          // bit p set iff X^2+Y^2 <= 1 on 5x5 grid
#define OUT_CI_STRIDE (NROT * C_DIM * 200)   // 204800
#define WPAD 105                    // wbil row stride (105 % 32 = 9, conflict-free STS)

__device__ __constant__ int APLIST[NACT] = {2,6,7,8,10,11,12,13,14,16,17,18,22};

__global__ __launch_bounds__(TPB)
void gk_r8_kernel(const float* __restrict__ in_H,
                  const float* __restrict__ out_H,
                  const float* __restrict__ weight,
                  float* __restrict__ out)
{
    __shared__ float  slab[NROT * 800];        // [g][ci32][q25] 25.6 KB
    __shared__ float  wbil[CIN_CHUNK * WPAD];  // [ci][g*13+pa]  13.4 KB
    __shared__ float  ftab[OGRP * 8];
    __shared__ int    gtab[OGRP * 8];
    __shared__ float4 ctab[OGRP * NACT];
    __shared__ int4   qtab[OGRP * NACT];

    const int co      = blockIdx.x;
    const int ci_base = blockIdx.y * CIN_CHUNK;
    const int o_base  = blockIdx.z * OGRP;
    const int tid     = threadIdx.x;
    const int w       = tid >> 5;
    const int lane    = tid & 31;

    // ---- fill slab: float4 copy ----
    {
        const float4* __restrict__ w4 = (const float4*)weight;
#pragma unroll
        for (int k = 0; k < 7; ++k) {
            int f = tid + k * TPB;
            if (f < 1600) {
                int g = f / 200;
                int r = f - g * 200;
                size_t gb4 = ((size_t)((g * C_DIM + co) * C_DIM + ci_base) * PATCH) >> 2;
                *(float4*)&slab[g * 800 + r * 4] = w4[gb4 + r];
            }
        }
    }

    // ---- per-(oo,i) Gk lerp table ----
    if (tid < OGRP * 8) {
        const int oo = tid >> 3, i = tid & 7;
        const float outH  = out_H[o_base + oo];
        const float theta = in_H[i] - outH;
        const float tmod  = theta - floorf(theta * (1.0f / TWO_PI_F)) * TWO_PI_F;
        const float pos   = tmod * ((float)NROT / TWO_PI_F);
        int g0 = ((int)floorf(pos)) % NROT;
        if (g0 >= NROT) g0 -= NROT;
        ftab[tid] = pos - floorf(pos);
        gtab[tid] = g0;
    }

    // ---- per-(oo,pa) bilinear tables ----
    if (tid < OGRP * NACT) {
        const int oo = tid / NACT, pa = tid - oo * NACT;
        const int p  = APLIST[pa];
        const int px = p % KS, py = p / KS;
        const float X = -1.0f + 0.5f * (float)px;
        const float Y = -1.0f + 0.5f * (float)py;
        const float outH = out_H[o_base + oo];
        const float cc = cosf(-outH), ss = sinf(-outH);
        const float gx = cc * X - ss * Y;
        const float gy = ss * X + cc * Y;
        const float sx = fmaf(gx, 2.0f, 2.0f);
        const float sy = fmaf(gy, 2.0f, 2.0f);
        const float fxf = floorf(sx), fyf = floorf(sy);
        const float fx = sx - fxf, fy = sy - fyf;
        int x0 = min(max((int)fxf, 0), KS - 1);
        int y0 = min(max((int)fyf, 0), KS - 1);
        const int x1 = min(x0 + 1, KS - 1);
        const int y1 = min(y0 + 1, KS - 1);
        ctab[tid] = make_float4((1.0f - fy) * (1.0f - fx), (1.0f - fy) * fx,
                                fy * (1.0f - fx),          fy * fx);
        qtab[tid] = make_int4(y0 * KS + x0, y0 * KS + x1,
                              y1 * KS + x0, y1 * KS + x1);
    }

    // ---- packed per-lane r-chunk constants (2 regs, cheap extraction) ----
    unsigned ipack = 0, papack = 0, actm = 0;
#pragma unroll
    for (int rc = 0; rc < 7; ++rc) {
        const int r  = rc * 32 + lane;
        const int ri = (r < 200) ? r : 0;
        const int ii = ri / 25;
        const int p  = ri - ii * 25;
        ipack  |= (unsigned)ii << (3 * rc);
        papack |= (unsigned)__popc(ACT_MASK & ((1u << p) - 1u)) << (4 * rc);
        if (r < 200 && ((ACT_MASK >> p) & 1u)) actm |= (1u << rc);
    }

    __syncthreads();

    for (int oo = 0; oo < OGRP; ++oo) {
        // ---- phase A: bilinear gather per g-slab -> wbil[ci][g*13+pa] ----
        {
            const float* srow = slab + w * 800 + lane * PATCH;   // stride 25: CF
            float* wrow = wbil + lane * WPAD + w * NACT;
#pragma unroll
            for (int pa = 0; pa < NACT; ++pa) {
                const int4   q = qtab[oo * NACT + pa];   // broadcast
                const float4 c = ctab[oo * NACT + pa];   // broadcast
                float v;
                v = c.x * srow[q.x];
                v = fmaf(c.y, srow[q.y], v);
                v = fmaf(c.z, srow[q.z], v);
                v = fmaf(c.w, srow[q.w], v);
                wrow[pa] = v;                            // stride 105: CF
            }
        }
        __syncthreads();

        // ---- phase BC: rc-outer / cj-inner (minimal live registers) ----
        float* obase = out + (size_t)ci_base * OUT_CI_STRIDE
                           + (size_t)((o_base + oo) * C_DIM + co) * 200
                           + (size_t)w * OUT_CI_STRIDE;         // ci = w + cj*8
#pragma unroll
        for (int rc = 0; rc < 7; ++rc) {
            const int r = rc * 32 + lane;
            if (r < 200) {
                const int ii = (ipack >> (3 * rc)) & 7;
                const int pa = (papack >> (4 * rc)) & 15;
                const int t  = oo * 8 + ii;
                const float fr = ftab[t];                // broadcast (<=2 addrs/warp)
                const int g0 = gtab[t];
                const int g1 = (g0 + 1) & (NROT - 1);
                const int o0 = g0 * NACT + pa;
                const int o1 = g1 * NACT + pa;
                const bool act = (actm >> rc) & 1u;
#pragma unroll
                for (int cj = 0; cj < 4; ++cj) {
                    const int cioff = (w + cj * 8) * WPAD;
                    float v = 0.0f;
                    if (act) {
                        const float v0 = wbil[cioff + o0];
                        const float v1 = wbil[cioff + o1];
                        v = fmaf(fr, v1 - v0, v0);
                    }
                    obase[(size_t)(cj * 8) * OUT_CI_STRIDE + r] = v;   // coalesced
                }
            }
        }
        __syncthreads();
    }
}

extern "C" void kernel_launch(void* const* d_in, const int* in_sizes, int n_in,
                              void* d_out, int out_size)
{
    const float* in_H   = (const float*)d_in[0];
    const float* out_H  = (const float*)d_in[1];
    const float* weight = (const float*)d_in[2];
    float* out = (float*)d_out;

    dim3 grid(C_DIM, C_DIM / CIN_CHUNK, NROT / OGRP);   // 1024 blocks
    gk_r8_kernel<<<grid, TPB>>>(in_H, out_H, weight, out);
}

// round 9
// speedup vs baseline: 1.6157x; 1.6157x over previous
#include <cuda_runtime.h>

#define TWO_PI_F 6.283185307179586f
#define NROT 8
#define C_DIM 128
#define KS 5
#define PATCH 25
#define TPB 256
#define CIN_CHUNK 32
#define NACT 13
#define OGRP 4
#define ACT_MASK 0x477DC4u          // bit p set iff X^2+Y^2 <= 1 on 5x5 grid
#define OUT_CI_STRIDE (NROT * C_DIM * 200)   // 204800
#define WPAD 105                    // wbil row stride (105 % 32 = 9, conflict-free)

__device__ __constant__ int APLIST[NACT] = {2,6,7,8,10,11,12,13,14,16,17,18,22};

__device__ __forceinline__ unsigned smem_u32(const void* p) {
    return (unsigned)__cvta_generic_to_shared(p);
}

__global__ __launch_bounds__(TPB)
void gk_r9_kernel(const float* __restrict__ in_H,
                  const float* __restrict__ out_H,
                  const float* __restrict__ weight,
                  float* __restrict__ out)
{
    __shared__ float  slab[NROT * 800];            // [g][ci32][q25] 25.6 KB
    __shared__ float  wbil[2][CIN_CHUNK * WPAD];   // double-buffered, 2x13.4 KB
    __shared__ float  ftab[OGRP * 8];
    __shared__ int    gtab[OGRP * 8];
    __shared__ float4 ctab[OGRP * NACT];
    __shared__ int4   qtab[OGRP * NACT];

    const int co      = blockIdx.x;
    const int ci_base = blockIdx.y * CIN_CHUNK;
    const int o_base  = blockIdx.z * OGRP;
    const int tid     = threadIdx.x;
    const int w       = tid >> 5;
    const int lane    = tid & 31;

    // ---- fill slab with cp.async (no register round-trip; overlaps table math) ----
    {
        const float4* __restrict__ w4 = (const float4*)weight;
#pragma unroll
        for (int k = 0; k < 7; ++k) {
            int f = tid + k * TPB;                  // float4 index 0..1599
            if (f < 1600) {
                int g = f / 200;
                int r = f - g * 200;
                size_t gb4 = ((size_t)((g * C_DIM + co) * C_DIM + ci_base) * PATCH) >> 2;
                unsigned dst = smem_u32(&slab[g * 800 + r * 4]);
                asm volatile("cp.async.cg.shared.global [%0], [%1], 16;\n"
                             :: "r"(dst), "l"(w4 + gb4 + r) : "memory");
            }
        }
        asm volatile("cp.async.commit_group;\n" ::: "memory");
    }

    // ---- per-(oo,i) Gk lerp table ----
    if (tid < OGRP * 8) {
        const int oo = tid >> 3, i = tid & 7;
        const float outH  = out_H[o_base + oo];
        const float theta = in_H[i] - outH;
        const float tmod  = theta - floorf(theta * (1.0f / TWO_PI_F)) * TWO_PI_F;
        const float pos   = tmod * ((float)NROT / TWO_PI_F);
        int g0 = ((int)floorf(pos)) % NROT;
        if (g0 >= NROT) g0 -= NROT;
        ftab[tid] = pos - floorf(pos);
        gtab[tid] = g0;
    }

    // ---- per-(oo,pa) bilinear tables ----
    if (tid < OGRP * NACT) {
        const int oo = tid / NACT, pa = tid - oo * NACT;
        const int p  = APLIST[pa];
        const int px = p % KS, py = p / KS;
        const float X = -1.0f + 0.5f * (float)px;
        const float Y = -1.0f + 0.5f * (float)py;
        const float outH = out_H[o_base + oo];
        const float cc = cosf(-outH), ss = sinf(-outH);
        const float gx = cc * X - ss * Y;
        const float gy = ss * X + cc * Y;
        const float sx = fmaf(gx, 2.0f, 2.0f);
        const float sy = fmaf(gy, 2.0f, 2.0f);
        const float fxf = floorf(sx), fyf = floorf(sy);
        const float fx = sx - fxf, fy = sy - fyf;
        int x0 = min(max((int)fxf, 0), KS - 1);
        int y0 = min(max((int)fyf, 0), KS - 1);
        const int x1 = min(x0 + 1, KS - 1);
        const int y1 = min(y0 + 1, KS - 1);
        ctab[tid] = make_float4((1.0f - fy) * (1.0f - fx), (1.0f - fy) * fx,
                                fy * (1.0f - fx),          fy * fx);
        qtab[tid] = make_int4(y0 * KS + x0, y0 * KS + x1,
                              y1 * KS + x0, y1 * KS + x1);
    }

    // ---- packed per-lane r-chunk constants ----
    unsigned ipack = 0, papack = 0, actm = 0;
#pragma unroll
    for (int rc = 0; rc < 7; ++rc) {
        const int r  = rc * 32 + lane;
        const int ri = (r < 200) ? r : 0;
        const int ii = ri / 25;
        const int p  = ri - ii * 25;
        ipack  |= (unsigned)ii << (3 * rc);
        papack |= (unsigned)__popc(ACT_MASK & ((1u << p) - 1u)) << (4 * rc);
        if (r < 200 && ((ACT_MASK >> p) & 1u)) actm |= (1u << rc);
    }

    asm volatile("cp.async.wait_group 0;\n" ::: "memory");
    __syncthreads();

#pragma unroll
    for (int oo = 0; oo < OGRP; ++oo) {
        float* wbuf = wbil[oo & 1];

        // ---- phase A: bilinear gather per g-slab -> wbuf[ci][g*13+pa] ----
        {
            const float* srow = slab + w * 800 + lane * PATCH;   // stride 25: CF
            float* wrow = wbuf + lane * WPAD + w * NACT;
#pragma unroll
            for (int pa = 0; pa < NACT; ++pa) {
                const int4   q = qtab[oo * NACT + pa];   // broadcast
                const float4 c = ctab[oo * NACT + pa];   // broadcast
                float v;
                v = c.x * srow[q.x];
                v = fmaf(c.y, srow[q.y], v);
                v = fmaf(c.z, srow[q.z], v);
                v = fmaf(c.w, srow[q.w], v);
                wrow[pa] = v;                            // stride 105: CF
            }
        }
        __syncthreads();    // A(oo) complete before BC(oo); next A writes other buffer

        // ---- phase BC: Gk lerp + direct coalesced store (R6 structure) ----
        float fr[7]; int off0[7], off1[7];
#pragma unroll
        for (int rc = 0; rc < 7; ++rc) {
            const int ii = (ipack >> (3 * rc)) & 7;
            const int pa = (papack >> (4 * rc)) & 15;
            const int t  = oo * 8 + ii;
            fr[rc] = ftab[t];
            const int g0 = gtab[t];
            const int g1 = (g0 + 1) & (NROT - 1);
            off0[rc] = g0 * NACT + pa;
            off1[rc] = g1 * NACT + pa;
        }

        float* obase = out + (size_t)ci_base * OUT_CI_STRIDE
                           + (size_t)((o_base + oo) * C_DIM + co) * 200;
#pragma unroll
        for (int cj = 0; cj < 4; ++cj) {
            const int ci = w + cj * 8;
            const float* wrow = wbuf + ci * WPAD;
            float* orow = obase + (size_t)ci * OUT_CI_STRIDE;
#pragma unroll
            for (int rc = 0; rc < 7; ++rc) {
                const int r = rc * 32 + lane;
                if (r < 200) {
                    float v = 0.0f;
                    if ((actm >> rc) & 1u) {
                        const float v0 = wrow[off0[rc]];
                        const float v1 = wrow[off1[rc]];
                        v = fmaf(fr[rc], v1 - v0, v0);
                    }
                    orow[r] = v;                         // coalesced
                }
            }
        }
        // no trailing sync: next A targets the other wbil buffer
    }
}

extern "C" void kernel_launch(void* const* d_in, const int* in_sizes, int n_in,
                              void* d_out, int out_size)
{
    const float* in_H   = (const float*)d_in[0];
    const float* out_H  = (const float*)d_in[1];
    const float* weight = (const float*)d_in[2];
    float* out = (float*)d_out;

    dim3 grid(C_DIM, C_DIM / CIN_CHUNK, NROT / OGRP);   // 1024 blocks
    gk_r9_kernel<<<grid, TPB>>>(in_H, out_H, weight, out);
}